// round 11
// baseline (speedup 1.0000x reference)
#include <cuda_runtime.h>
#include <math.h>

// Problem constants (shapes fixed by the dataset)
#define NUM_CLASSES 100000
#define ROWF 52      // floats per scratch row: [mn0,mx0,...,mn24,mx24,area,pad]
#define ROW4 13      // float4 per scratch row
#define PPB  64      // pairs per tile: 64*26 = 1664 = 13*128 -> exact unrolled gather
#define NTHR 128     // threads per block
#define STAGES 4     // smem ring depth: 4*64*27*16 = 110.6KB -> 2 blocks/SM
#define STRIDE4 27   // smem stride (float4) per pair; odd word stride -> conflict-free LDS.128
#define EMB_BOUND 10000.0f

// Scratch: transformed table (20.8 MB) + accumulator. Static __device__ globals
// (runtime allocation is forbidden by the harness).
__device__ float4 g_scratch[NUM_CLASSES * ROW4];
__device__ double g_acc;

// ---------------------------------------------------------------------------
// Kernel 1: transform class_embeds -> [mn,mx interleaved, area] rows.
// One warp per row: lanes 0..24 each own one dim; shfl-xor product for area.
// ---------------------------------------------------------------------------
__global__ __launch_bounds__(256)
void precompute_kernel(const float* __restrict__ embeds, int num_classes) {
    int gtid = blockIdx.x * blockDim.x + threadIdx.x;
    if (gtid == 0) g_acc = 0.0;

    int warp = gtid >> 5;
    int lane = threadIdx.x & 31;
    if (warp >= num_classes) return;

    float c = 0.0f, o = 0.0f, part = 1.0f;
    if (lane < 25) {
        c = embeds[warp * 50 + lane];
        o = fabsf(embeds[warp * 50 + 25 + lane]);
        part = 2.0f * o;
    }
    #pragma unroll
    for (int off = 16; off; off >>= 1)
        part *= __shfl_xor_sync(0xffffffffu, part, off);

    float* gs = (float*)g_scratch;
    if (lane < 25) {
        float2 v = make_float2(c - o, c + o);                // (mn, mx)
        *(float2*)(gs + (size_t)warp * ROWF + 2 * lane) = v;
    }
    if (lane == 25) {
        gs[(size_t)warp * ROWF + 50] = part;
        gs[(size_t)warp * ROWF + 51] = 0.0f;
    }
}

// ---------------------------------------------------------------------------
// Kernel 2: PERSISTENT pair kernel, 4-stage cp.async ring, prefetch dist ~3.
// Steady state per iteration n:
//   wait_group 2  -> tile n resident (tiles n+1, n+2 in flight)
//   compute tile n
//   stage idx + issue gather for tile n+3 (one commit_group per thread ALWAYS,
//   so the constant wait_group depth stays well-defined)
// ---------------------------------------------------------------------------
__device__ __forceinline__ void stage_idx(const int* __restrict__ nf1, int* sIdx,
                                          int g, int s, int tid, int nPairs) {
    int p0 = g * PPB;
    int np = nPairs - p0; if (np > PPB) np = PPB;
    if (tid < np) {
        int2 ij = ((const int2*)nf1)[p0 + tid];
        sIdx[s * 2 * PPB + 2 * tid]     = ij.x;
        sIdx[s * 2 * PPB + 2 * tid + 1] = ij.y;
    }
}

__device__ __forceinline__ void issue_gather(float4* sm4, const int* sIdx,
                                             int g, int s, int tid, int nPairs) {
    int p0 = g * PPB;
    int np = nPairs - p0; if (np > PPB) np = PPB;
    const int* sI = &sIdx[s * 2 * PPB];
    float4* dstB  = &sm4[s * PPB * STRIDE4];
    if (np == PPB) {
        #pragma unroll
        for (int k = 0; k < 13; k++) {
            int i     = tid + k * NTHR;
            int pair  = i / 26;
            int sub   = i - pair * 26;
            int which = (sub >= 13) ? 1 : 0;
            int chunk = sub - which * 13;
            int row   = sI[2 * pair + which];
            const float4* src = &g_scratch[(size_t)row * ROW4 + chunk];
            unsigned dst = (unsigned)__cvta_generic_to_shared(&dstB[pair * STRIDE4 + sub]);
            asm volatile("cp.async.cg.shared.global [%0], [%1], 16;\n" :: "r"(dst), "l"(src));
        }
    } else {
        int total = np * 26;
        for (int i = tid; i < total; i += NTHR) {
            int pair  = i / 26;
            int sub   = i - pair * 26;
            int which = (sub >= 13) ? 1 : 0;
            int chunk = sub - which * 13;
            int row   = sI[2 * pair + which];
            const float4* src = &g_scratch[(size_t)row * ROW4 + chunk];
            unsigned dst = (unsigned)__cvta_generic_to_shared(&dstB[pair * STRIDE4 + sub]);
            asm volatile("cp.async.cg.shared.global [%0], [%1], 16;\n" :: "r"(dst), "l"(src));
        }
    }
}

__global__ __launch_bounds__(NTHR, 2)
void pair_kernel(const int* __restrict__ nf1, int nPairs, int nTiles) {
    extern __shared__ float4 sm4[];                     // STAGES*PPB*STRIDE4 float4
    int* sIdx = (int*)&sm4[STAGES * PPB * STRIDE4];     // STAGES*2*PPB ints

    int tid = threadIdx.x;
    int b   = blockIdx.x;
    int G   = gridDim.x;
    float ssq = 0.0f;

    // ---- prologue: stage tiles for local n = 0,1,2 ----
    #pragma unroll
    for (int m = 0; m < 3; m++) {
        int g = b + m * G;
        if (g < nTiles) stage_idx(nf1, sIdx, g, m, tid, nPairs);
    }
    __syncthreads();
    #pragma unroll
    for (int m = 0; m < 3; m++) {
        int g = b + m * G;
        if (g < nTiles) issue_gather(sm4, sIdx, g, m, tid, nPairs);
        asm volatile("cp.async.commit_group;\n" ::: "memory");   // one group ALWAYS
    }

    // ---- main loop ----
    for (int n = 0;; n++) {
        int g = b + n * G;
        if (g >= nTiles) break;

        asm volatile("cp.async.wait_group 2;\n" ::: "memory");   // tile n done (per-thread)
        __syncthreads();                                         // visible to all threads

        // compute tile n from stage n&3
        {
            int p0 = g * PPB;
            int np = nPairs - p0; if (np > PPB) np = PPB;
            if (tid < np) {
                const float4* P = &sm4[(n & 3) * PPB * STRIDE4 + tid * STRIDE4];
                float prod = 1.0f;
                #pragma unroll
                for (int j = 0; j < 12; j++) {
                    float4 c = P[j];
                    float4 d = P[13 + j];
                    prod *= fmaxf(fminf(c.y, d.y) - fmaxf(c.x, d.x), 0.0f);
                    prod *= fmaxf(fminf(c.w, d.w) - fmaxf(c.z, d.z), 0.0f);
                }
                float4 c12 = P[12];
                float4 d12 = P[25];
                prod *= fmaxf(fminf(c12.y, d12.y) - fmaxf(c12.x, d12.x), 0.0f);
                float area = c12.z;

                float loss;
                if (area == 0.0f)      loss = 0.0f;
                else if (isinf(area))  loss = 1.0f - prod * (1.0f / (2.0f * EMB_BOUND));
                else                   loss = 1.0f - prod / area;
                loss = fmaxf(loss, 0.0f);
                ssq += loss * loss;
            }
        }

        // stage + issue tile n+3 into ring slot (n+3)&3 (buffer of tile n-1,
        // whose compute finished before iteration n's barrier above)
        int g3 = b + (n + 3) * G;
        if (g3 < nTiles) stage_idx(nf1, sIdx, g3, (n + 3) & 3, tid, nPairs);
        __syncthreads();                                         // idx visible to gatherers
        if (g3 < nTiles) issue_gather(sm4, sIdx, g3, (n + 3) & 3, tid, nPairs);
        asm volatile("cp.async.commit_group;\n" ::: "memory");   // one group ALWAYS
    }

    // ---- epilogue: one reduction + one atomic per block ----
    #pragma unroll
    for (int off = 16; off; off >>= 1)
        ssq += __shfl_down_sync(0xffffffffu, ssq, off);

    __shared__ float warpSums[NTHR / 32];
    if ((tid & 31) == 0) warpSums[tid >> 5] = ssq;
    __syncthreads();
    if (tid == 0) {
        float v = warpSums[0] + warpSums[1] + warpSums[2] + warpSums[3];
        atomicAdd(&g_acc, (double)v);
    }
}

// ---------------------------------------------------------------------------
// Kernel 3: finalize
// ---------------------------------------------------------------------------
__global__ void finalize_kernel(float* __restrict__ out) {
    out[0] = sqrtf((float)g_acc);
}

extern "C" void kernel_launch(void* const* d_in, const int* in_sizes, int n_in,
                              void* d_out, int out_size) {
    const float* embeds = (const float*)d_in[0];   // class_embeds [100000, 50]
    const int*   nf1    = (const int*)d_in[1];     // nf1_data    [2000000, 2]

    int num_classes = in_sizes[0] / 50;
    if (num_classes > NUM_CLASSES) num_classes = NUM_CLASSES;
    int nPairs = in_sizes[1] / 2;

    // Precompute transformed table (warp per row) + zero accumulator
    int pre_blocks = (num_classes * 32 + 255) / 256;
    precompute_kernel<<<pre_blocks, 256>>>(embeds, num_classes);

    // Persistent pair kernel: 4-stage ring, 110.6KB+2KB dyn smem, 2 blocks/SM
    int smem_bytes = STAGES * PPB * STRIDE4 * (int)sizeof(float4)
                   + STAGES * 2 * PPB * (int)sizeof(int);
    cudaFuncSetAttribute(pair_kernel,
                         cudaFuncAttributeMaxDynamicSharedMemorySize, smem_bytes);

    int num_sms = 148;
    cudaDeviceGetAttribute(&num_sms, cudaDevAttrMultiProcessorCount, 0);
    int nTiles = (nPairs + PPB - 1) / PPB;
    int grid = 2 * num_sms;
    if (grid > nTiles) grid = nTiles;
    if (grid < 1) grid = 1;

    pair_kernel<<<grid, NTHR, smem_bytes>>>(nf1, nPairs, nTiles);

    finalize_kernel<<<1, 1>>>((float*)d_out);
}

// round 17
// speedup vs baseline: 1.1774x; 1.1774x over previous
#include <cuda_runtime.h>
#include <math.h>

// Problem constants (shapes fixed by the dataset)
#define NUM_CLASSES 100000
#define ROWF 52      // floats per scratch row: [mn0,mx0,...,mn24,mx24,area,pad]
#define ROW4 13      // float4 per scratch row
#define PPB  80      // pairs per tile
#define STAGES 3     // smem ring depth: 3*80*27*16 = 103.7KB -> 2 blocks/SM
#define NTHR 256     // 4 consumer warps + 4 producer warps
#define NPROD 128    // producer threads
#define STRIDE4 27   // smem stride (float4) per pair; odd word stride -> conflict-free LDS.128
#define IDXS (2*PPB) // ints per stage of the idx buffer
#define EMB_BOUND 10000.0f

// Scratch: transformed table (20.8 MB) + accumulator. Static __device__ globals
// (runtime allocation is forbidden by the harness).
__device__ float4 g_scratch[NUM_CLASSES * ROW4];
__device__ double g_acc;

// ---- mbarrier helpers ----
#define MBAR_INIT(addr, cnt) \
    asm volatile("mbarrier.init.shared.b64 [%0], %1;" :: "r"(addr), "r"(cnt) : "memory")
#define MBAR_ARRIVE(addr) \
    asm volatile("mbarrier.arrive.shared.b64 _, [%0];" :: "r"(addr) : "memory")
#define MBAR_WAIT(addr, parity) do {                                          \
    unsigned _mb = (addr); unsigned _ph = (parity); unsigned _done;           \
    asm volatile("{\n\t.reg .pred p;\n\t"                                     \
        "mbarrier.try_wait.parity.acquire.cta.shared::cta.b64 p, [%1], %2;\n\t" \
        "selp.b32 %0, 1, 0, p;\n\t}"                                          \
        : "=r"(_done) : "r"(_mb), "r"(_ph) : "memory");                       \
    if (!_done) {                                                             \
        asm volatile("{\n\t.reg .pred P1;\n\t"                                \
            "WL_%=:\n\t"                                                      \
            "mbarrier.try_wait.parity.acquire.cta.shared::cta.b64 P1, [%0], %1, 0x989680;\n\t" \
            "@P1 bra.uni WD_%=;\n\t"                                          \
            "bra.uni WL_%=;\n\t"                                              \
            "WD_%=:\n\t}" :: "r"(_mb), "r"(_ph) : "memory");                  \
    }                                                                         \
} while (0)

// ---------------------------------------------------------------------------
// Kernel 1: transform class_embeds -> [mn,mx interleaved, area] rows.
// One warp per row: lanes 0..24 each own one dim; shfl-xor product for area.
// ---------------------------------------------------------------------------
__global__ __launch_bounds__(256)
void precompute_kernel(const float* __restrict__ embeds, int num_classes) {
    int gtid = blockIdx.x * blockDim.x + threadIdx.x;
    if (gtid == 0) g_acc = 0.0;

    int warp = gtid >> 5;
    int lane = threadIdx.x & 31;
    if (warp >= num_classes) return;

    float c = 0.0f, o = 0.0f, part = 1.0f;
    if (lane < 25) {
        c = embeds[warp * 50 + lane];
        o = fabsf(embeds[warp * 50 + 25 + lane]);
        part = 2.0f * o;
    }
    #pragma unroll
    for (int off = 16; off; off >>= 1)
        part *= __shfl_xor_sync(0xffffffffu, part, off);

    float* gs = (float*)g_scratch;
    if (lane < 25) {
        float2 v = make_float2(c - o, c + o);                // (mn, mx)
        *(float2*)(gs + (size_t)warp * ROWF + 2 * lane) = v;
    }
    if (lane == 25) {
        gs[(size_t)warp * ROWF + 50] = part;
        gs[(size_t)warp * ROWF + 51] = 0.0f;
    }
}

// ---------------------------------------------------------------------------
// Kernel 2: PERSISTENT warp-specialized pair kernel.
// Warps 0-3 (128 thr): consumers — wait full[s], compute, arrive empty[s].
// Warps 4-7 (128 thr): producers — wait empty[s], stage idx (named bar 1),
//   issue cp.async gather, cp.async.mbarrier.arrive.NOINC on full[s].
// (.noinc is load-bearing: the default form pre-increments the pending count
//  for a net-zero effect against our count=NPROD init -> R13's deadlock.)
// ---------------------------------------------------------------------------
__global__ __launch_bounds__(NTHR, 2)
void pair_kernel(const int* __restrict__ nf1, int nPairs, int nTiles) {
    extern __shared__ float4 sm4[];                       // STAGES*PPB*STRIDE4 float4
    int*      sIdx = (int*)&sm4[STAGES * PPB * STRIDE4];  // STAGES*IDXS ints
    unsigned long long* mbar = (unsigned long long*)&sIdx[STAGES * IDXS]; // 2*STAGES

    int tid = threadIdx.x;
    unsigned smem_base;
    asm("{ .reg .u64 t; cvta.to.shared.u64 t, %1; cvt.u32.u64 %0, t; }"
        : "=r"(smem_base) : "l"((void*)mbar));
    // full[s] at smem_base + s*16, empty[s] at smem_base + s*16 + 8

    if (tid == 0) {
        #pragma unroll
        for (int s = 0; s < STAGES; s++) {
            MBAR_INIT(smem_base + s * 16,     NPROD);         // full: producer arrivals
            MBAR_INIT(smem_base + s * 16 + 8, NTHR - NPROD);  // empty: consumer arrivals
        }
    }
    __syncthreads();

    int b = blockIdx.x;
    int G = gridDim.x;
    float ssq = 0.0f;

    if (tid >= NPROD) {
        // ================= PRODUCER =================
        int ptid = tid - NPROD;
        int st = 0, ph = 1;                 // empty-wait phase starts at 1 (passes immediately)
        for (int n = 0;; n++) {
            int g = b + n * G;
            if (g >= nTiles) break;
            int p0 = g * PPB;
            int np = nPairs - p0; if (np > PPB) np = PPB;

            MBAR_WAIT(smem_base + st * 16 + 8, (unsigned)ph);   // stage free

            if (ptid < np) {
                int2 ij = ((const int2*)nf1)[p0 + ptid];
                sIdx[st * IDXS + 2 * ptid]     = ij.x;
                sIdx[st * IDXS + 2 * ptid + 1] = ij.y;
            }
            asm volatile("bar.sync 1, %0;" :: "n"(NPROD) : "memory"); // producers only

            const int* sI  = &sIdx[st * IDXS];
            float4* dstB   = &sm4[st * PPB * STRIDE4];
            int total = np * 26;
            #pragma unroll
            for (int k = 0; k < 17; k++) {                 // 80*26=2080 -> 16.25*128
                int i = ptid + k * NPROD;
                if (i < total) {
                    int pair  = i / 26;
                    int sub   = i - pair * 26;
                    int which = (sub >= 13) ? 1 : 0;
                    int chunk = sub - which * 13;
                    int row   = sI[2 * pair + which];
                    const float4* src = &g_scratch[(size_t)row * ROW4 + chunk];
                    unsigned dst = (unsigned)__cvta_generic_to_shared(
                        &dstB[pair * STRIDE4 + sub]);
                    asm volatile("cp.async.cg.shared.global [%0], [%1], 16;\n"
                                 :: "r"(dst), "l"(src));
                }
            }
            // decrementing arrive when this thread's cp.asyncs complete
            asm volatile("cp.async.mbarrier.arrive.noinc.shared::cta.b64 [%0];"
                         :: "r"(smem_base + st * 16) : "memory");

            if (++st == STAGES) { st = 0; ph ^= 1; }
        }
    } else {
        // ================= CONSUMER =================
        int st = 0, ph = 0;
        for (int n = 0;; n++) {
            int g = b + n * G;
            if (g >= nTiles) break;
            int p0 = g * PPB;
            int np = nPairs - p0; if (np > PPB) np = PPB;

            MBAR_WAIT(smem_base + st * 16, (unsigned)ph);   // tile data ready

            if (tid < np) {
                const float4* P = &sm4[st * PPB * STRIDE4 + tid * STRIDE4];
                float prod = 1.0f;
                #pragma unroll
                for (int j = 0; j < 12; j++) {
                    float4 c = P[j];
                    float4 d = P[13 + j];
                    prod *= fmaxf(fminf(c.y, d.y) - fmaxf(c.x, d.x), 0.0f);
                    prod *= fmaxf(fminf(c.w, d.w) - fmaxf(c.z, d.z), 0.0f);
                }
                float4 c12 = P[12];
                float4 d12 = P[25];
                prod *= fmaxf(fminf(c12.y, d12.y) - fmaxf(c12.x, d12.x), 0.0f);
                float area = c12.z;

                float loss;
                if (area == 0.0f)      loss = 0.0f;
                else if (isinf(area))  loss = 1.0f - prod * (1.0f / (2.0f * EMB_BOUND));
                else                   loss = 1.0f - prod / area;
                loss = fmaxf(loss, 0.0f);
                ssq += loss * loss;
            }
            MBAR_ARRIVE(smem_base + st * 16 + 8);           // release stage

            if (++st == STAGES) { st = 0; ph ^= 1; }
        }
    }

    // ---- epilogue: block reduction (producers contribute 0) ----
    __syncthreads();
    #pragma unroll
    for (int off = 16; off; off >>= 1)
        ssq += __shfl_down_sync(0xffffffffu, ssq, off);

    __shared__ float warpSums[NTHR / 32];
    if ((tid & 31) == 0) warpSums[tid >> 5] = ssq;
    __syncthreads();
    if (tid == 0) {
        float v = 0.0f;
        #pragma unroll
        for (int w = 0; w < NTHR / 32; w++) v += warpSums[w];
        atomicAdd(&g_acc, (double)v);
    }
}

// ---------------------------------------------------------------------------
// Kernel 3: finalize
// ---------------------------------------------------------------------------
__global__ void finalize_kernel(float* __restrict__ out) {
    out[0] = sqrtf((float)g_acc);
}

extern "C" void kernel_launch(void* const* d_in, const int* in_sizes, int n_in,
                              void* d_out, int out_size) {
    const float* embeds = (const float*)d_in[0];   // class_embeds [100000, 50]
    const int*   nf1    = (const int*)d_in[1];     // nf1_data    [2000000, 2]

    int num_classes = in_sizes[0] / 50;
    if (num_classes > NUM_CLASSES) num_classes = NUM_CLASSES;
    int nPairs = in_sizes[1] / 2;

    // Precompute transformed table (warp per row) + zero accumulator
    int pre_blocks = (num_classes * 32 + 255) / 256;
    precompute_kernel<<<pre_blocks, 256>>>(embeds, num_classes);

    // Warp-specialized persistent pair kernel
    int smem_bytes = STAGES * PPB * STRIDE4 * (int)sizeof(float4)
                   + STAGES * IDXS * (int)sizeof(int)
                   + 2 * STAGES * (int)sizeof(unsigned long long);
    cudaFuncSetAttribute(pair_kernel,
                         cudaFuncAttributeMaxDynamicSharedMemorySize, smem_bytes);

    int num_sms = 148;
    cudaDeviceGetAttribute(&num_sms, cudaDevAttrMultiProcessorCount, 0);
    int nTiles = (nPairs + PPB - 1) / PPB;
    int grid = 2 * num_sms;
    if (grid > nTiles) grid = nTiles;
    if (grid < 1) grid = 1;

    pair_kernel<<<grid, NTHR, smem_bytes>>>(nf1, nPairs, nTiles);

    finalize_kernel<<<1, 1>>>((float*)d_out);
}